// round 9
// baseline (speedup 1.0000x reference)
#include <cuda_runtime.h>
#include <stdint.h>

// StationSelectionAggregator:
//   schedule: [B, WIN, N_ST]  one-hot float32
//   csi:      [B, N_ST, N_SUB, WIN] float32
//   out:      [B, WIN, N_SUB] float32
//   out[b,w,s] = csi[b, t(b,w), s, w]  (exact selection; schedule one-hot).
//
// Structure = R1 exactly (best of 8 variants, 6.83 TB/s): tw smem stage,
// 4 batched gather LDGs/thread coalesced along w, 32x32 smem transpose,
// coalesced writes along s. Single change this round: __stcs on the output
// stores ONLY (writes have zero reuse; evict-first avoids L2 write-allocate
// churn against the latency-critical gather read stream). Reads stay plain
// (__ldcs on reads regressed in R2/R3).
#define B_    32
#define NST   8
#define NSUB  256
#define WIN   2048

__global__ __launch_bounds__(256)
void station_select_kernel(const float* __restrict__ sched,
                           const float* __restrict__ csi,
                           float* __restrict__ out) {
    // blockIdx.x : w tile (WIN/32 = 64)  [fastest -> contiguous lines across CTAs]
    // blockIdx.y : s tile (NSUB/32 = 8)
    // blockIdx.z : batch  (32)
    __shared__ float tile[32][33];   // [s_local][w_local], +1 pad
    __shared__ int   tw[32];         // selected station per w in this tile

    const int b   = blockIdx.z;
    const int w0  = blockIdx.x * 32;
    const int s0  = blockIdx.y * 32;
    const int tx  = threadIdx.x & 31;
    const int ty  = threadIdx.x >> 5;    // 0..7
    const int tid = threadIdx.x;

    // --- station index per w (exact: one-hot values are 0.0/1.0) ---
    if (tid < 32) {
        const float4* sp = reinterpret_cast<const float4*>(
            sched + ((size_t)b * WIN + (size_t)(w0 + tid)) * NST);
        const float4 a = sp[0];
        const float4 c = sp[1];
        const float tf = a.y + 2.f * a.z + 3.f * a.w +
                         4.f * c.x + 5.f * c.y + 6.f * c.z + 7.f * c.w;
        tw[tid] = (int)(tf + 0.5f);
    }
    __syncthreads();

    // --- gather reads: coalesced along w (tx), 4 independent LDGs batched ---
    const int t = tw[tx];
    const float* p = csi + ((size_t)(b * NST + t) * NSUB + (size_t)s0) * WIN
                         + (size_t)(w0 + tx);
    float v[4];
#pragma unroll
    for (int r = 0; r < 4; r++)
        v[r] = p[(size_t)(ty + r * 8) * WIN];

    // smem stage: bank = (sl + tx) & 31 -> conflict-free
#pragma unroll
    for (int r = 0; r < 4; r++)
        tile[ty + r * 8][tx] = v[r];
    __syncthreads();

    // --- transposed writes: coalesced along s (tx); evict-first stores ---
#pragma unroll
    for (int r = 0; r < 4; r++) {
        const int wl = ty + r * 8;   // w_local
        // LDS bank = (tx + wl) & 31 -> conflict-free
        __stcs(out + ((size_t)b * WIN + (size_t)(w0 + wl)) * NSUB
                   + (size_t)(s0 + tx),
               tile[tx][wl]);
    }
}

extern "C" void kernel_launch(void* const* d_in, const int* in_sizes, int n_in,
                              void* d_out, int out_size) {
    const float* sched = (const float*)d_in[0];
    const float* csi   = (const float*)d_in[1];
    if (n_in >= 2 && in_sizes[0] != 524288) {   // schedule = 32*2048*8 elems
        sched = (const float*)d_in[1];
        csi   = (const float*)d_in[0];
    }
    float* out = (float*)d_out;

    dim3 block(256, 1, 1);
    dim3 grid(WIN / 32, NSUB / 32, B_);
    station_select_kernel<<<grid, block>>>(sched, csi, out);
}

// round 10
// speedup vs baseline: 1.0177x; 1.0177x over previous
#include <cuda_runtime.h>
#include <cuda.h>
#include <stdint.h>

// StationSelectionAggregator:
//   schedule: [B, WIN, N_ST]  one-hot float32
//   csi:      [B, N_ST, N_SUB, WIN] float32
//   out:      [B, WIN, N_SUB] float32
//   out[b,w,s] = csi[b, t(b,w), s, w]  (exact selection; schedule one-hot).
//
// R10: TMA dense stage. The LDG gather's request stream (6 scattered partial
// lines per instruction across 8 planes) caps at 6.83 TB/s; 9 variants never
// beat it. TMA pulls the dense 8-plane block per tile as one sequential bulk
// copy (no registers, no occupancy pressure), and the selection moves to
// smem where it is conflict-free. Fallback to the best LDG kernel if the
// tensormap cannot be built.
#define B_    32
#define NST   8
#define NSUB  256
#define WIN   2048

// ---------------- device helpers ----------------
__device__ __forceinline__ uint32_t smem_u32(const void* p) {
    uint32_t a;
    asm("{ .reg .u64 t; cvta.to.shared.u64 t, %1; cvt.u32.u64 %0, t; }"
        : "=r"(a) : "l"(p));
    return a;
}

// ---------------- TMA kernel ----------------
__global__ __launch_bounds__(256)
void station_select_tma_kernel(const __grid_constant__ CUtensorMap tmap,
                               const float* __restrict__ sched,
                               float* __restrict__ out) {
    // blockIdx.x : w tile (64, fastest -> sequential lines chip-wide)
    // blockIdx.y : s tile (8),  blockIdx.z : batch (32)
    __shared__ __align__(128) float stage[NST][32][32];  // 32 KB, TMA dest
    __shared__ float tile[32][33];                       // transpose tile
    __shared__ int   tw[32];
    __shared__ __align__(8) uint64_t mbar;

    const int b   = blockIdx.z;
    const int w0  = blockIdx.x * 32;
    const int s0  = blockIdx.y * 32;
    const int tid = threadIdx.x;
    const int tx  = tid & 31;
    const int ty  = tid >> 5;

    const uint32_t mbar_a = smem_u32(&mbar);

    if (tid == 0) {
        asm volatile("mbarrier.init.shared.b64 [%0], %1;"
                     :: "r"(mbar_a), "r"(1) : "memory");
        asm volatile("mbarrier.arrive.expect_tx.shared.b64 _, [%0], %1;"
                     :: "r"(mbar_a), "r"((uint32_t)(NST * 32 * 32 * 4)) : "memory");
        asm volatile("cp.async.bulk.tensor.3d.shared::cta.global.tile.mbarrier::complete_tx::bytes "
                     "[%0], [%1, {%2, %3, %4}], [%5];"
                     :: "r"(smem_u32(stage)), "l"(&tmap),
                        "r"(w0), "r"(s0), "r"(b * NST), "r"(mbar_a)
                     : "memory");
    }
    // station decode overlaps the TMA fill (exact: one-hot values are 0.0/1.0)
    if (tid < 32) {
        const float4* sp = reinterpret_cast<const float4*>(
            sched + ((size_t)b * WIN + (size_t)(w0 + tid)) * NST);
        const float4 a = sp[0];
        const float4 c = sp[1];
        const float tf = a.y + 2.f * a.z + 3.f * a.w +
                         4.f * c.x + 5.f * c.y + 6.f * c.z + 7.f * c.w;
        tw[tid] = (int)(tf + 0.5f);
    }
    __syncthreads();   // publishes mbar init + tw to all threads

    // wait for TMA completion (parity 0; single-shot barrier)
    {
        uint32_t done;
        asm volatile("{\n\t.reg .pred p;\n\t"
                     "mbarrier.try_wait.parity.acquire.cta.shared::cta.b64 p, [%1], %2;\n\t"
                     "selp.b32 %0, 1, 0, p;\n\t}"
                     : "=r"(done) : "r"(mbar_a), "r"(0u) : "memory");
        if (!done) {
            asm volatile("{\n\t.reg .pred P1;\n\t"
                         "WL_%=:\n\t"
                         "mbarrier.try_wait.parity.acquire.cta.shared::cta.b64 P1, [%0], %1, 0x989680;\n\t"
                         "@P1 bra.uni WD_%=;\n\t"
                         "bra.uni WL_%=;\n\t"
                         "WD_%=:\n\t}"
                         :: "r"(mbar_a), "r"(0u) : "memory");
        }
    }

    // smem gather-select: lane tx picks its plane; byte addr % 128 == 4*tx
    // -> conflict-free regardless of t and s.
    const int t = tw[tx];
    float v[4];
#pragma unroll
    for (int r = 0; r < 4; r++)
        v[r] = stage[t][ty + r * 8][tx];

    // transpose tile: bank = (sl + tx) & 31 -> conflict-free
#pragma unroll
    for (int r = 0; r < 4; r++)
        tile[ty + r * 8][tx] = v[r];
    __syncthreads();

    // coalesced stores along s: bank = (tx + wl) & 31 -> conflict-free
#pragma unroll
    for (int r = 0; r < 4; r++) {
        const int wl = ty + r * 8;
        out[((size_t)b * WIN + (size_t)(w0 + wl)) * NSUB + (size_t)(s0 + tx)]
            = tile[tx][wl];
    }
}

// ---------------- fallback: R1 (best LDG kernel, 6.83 TB/s) ----------------
__global__ __launch_bounds__(256)
void station_select_ldg_kernel(const float* __restrict__ sched,
                               const float* __restrict__ csi,
                               float* __restrict__ out) {
    __shared__ float tile[32][33];
    __shared__ int   tw[32];

    const int b   = blockIdx.z;
    const int w0  = blockIdx.x * 32;
    const int s0  = blockIdx.y * 32;
    const int tid = threadIdx.x;
    const int tx  = tid & 31;
    const int ty  = tid >> 5;

    if (tid < 32) {
        const float4* sp = reinterpret_cast<const float4*>(
            sched + ((size_t)b * WIN + (size_t)(w0 + tid)) * NST);
        const float4 a = sp[0];
        const float4 c = sp[1];
        const float tf = a.y + 2.f * a.z + 3.f * a.w +
                         4.f * c.x + 5.f * c.y + 6.f * c.z + 7.f * c.w;
        tw[tid] = (int)(tf + 0.5f);
    }
    __syncthreads();

    const int t = tw[tx];
    const float* p = csi + ((size_t)(b * NST + t) * NSUB + (size_t)s0) * WIN
                         + (size_t)(w0 + tx);
    float v[4];
#pragma unroll
    for (int r = 0; r < 4; r++)
        v[r] = p[(size_t)(ty + r * 8) * WIN];
#pragma unroll
    for (int r = 0; r < 4; r++)
        tile[ty + r * 8][tx] = v[r];
    __syncthreads();

#pragma unroll
    for (int r = 0; r < 4; r++) {
        const int wl = ty + r * 8;
        out[((size_t)b * WIN + (size_t)(w0 + wl)) * NSUB + (size_t)(s0 + tx)]
            = tile[tx][wl];
    }
}

// ---------------- host ----------------
typedef CUresult (*tmap_encode_fn)(
    CUtensorMap*, CUtensorMapDataType, cuuint32_t, void*,
    const cuuint64_t*, const cuuint64_t*, const cuuint32_t*, const cuuint32_t*,
    CUtensorMapInterleave, CUtensorMapSwizzle, CUtensorMapL2promotion,
    CUtensorMapFloatOOBfill);

extern "C" void kernel_launch(void* const* d_in, const int* in_sizes, int n_in,
                              void* d_out, int out_size) {
    const float* sched = (const float*)d_in[0];
    const float* csi   = (const float*)d_in[1];
    if (n_in >= 2 && in_sizes[0] != 524288) {   // schedule = 32*2048*8 elems
        sched = (const float*)d_in[1];
        csi   = (const float*)d_in[0];
    }
    float* out = (float*)d_out;

    dim3 block(256, 1, 1);
    dim3 grid(WIN / 32, NSUB / 32, B_);

    // Build the tensormap for csi viewed as [W=2048][S=256][planes=256].
    void* fn = nullptr;
    cudaDriverEntryPointQueryResult qr = cudaDriverEntryPointSymbolNotFound;
#if CUDART_VERSION >= 12050
    cudaGetDriverEntryPointByVersion("cuTensorMapEncodeTiled", &fn, 12000,
                                     cudaEnableDefault, &qr);
#else
    cudaGetDriverEntryPoint("cuTensorMapEncodeTiled", &fn,
                            cudaEnableDefault, &qr);
#endif
    bool ok = false;
    CUtensorMap tmap;
    if (fn != nullptr && qr == cudaDriverEntryPointSuccess) {
        cuuint64_t dims[3]    = {WIN, NSUB, (cuuint64_t)B_ * NST};
        cuuint64_t strides[2] = {(cuuint64_t)WIN * 4,
                                 (cuuint64_t)WIN * NSUB * 4};
        cuuint32_t box[3]     = {32, 32, NST};
        cuuint32_t es[3]      = {1, 1, 1};
        ok = ((tmap_encode_fn)fn)(&tmap, CU_TENSOR_MAP_DATA_TYPE_FLOAT32, 3,
                                  (void*)csi, dims, strides, box, es,
                                  CU_TENSOR_MAP_INTERLEAVE_NONE,
                                  CU_TENSOR_MAP_SWIZZLE_NONE,
                                  CU_TENSOR_MAP_L2_PROMOTION_L2_128B,
                                  CU_TENSOR_MAP_FLOAT_OOB_FILL_NONE)
             == CUDA_SUCCESS;
    }

    if (ok) {
        station_select_tma_kernel<<<grid, block>>>(tmap, sched, out);
    } else {
        station_select_ldg_kernel<<<grid, block>>>(sched, csi, out);
    }
}